// round 15
// baseline (speedup 1.0000x reference)
#include <cuda_runtime.h>
#include <cuda_fp16.h>
#include <math.h>
#include <stdint.h>

// ---------------------------------------------------------------------------
// Problem constants
// ---------------------------------------------------------------------------
#define BATCH   8
#define SEQ     2048
#define DIM     512
#define NTOK    (BATCH * SEQ)          // 16384

// GEMM tiling (mma.sync m16n8k16 fp16)
#define BM 128
#define BN 128
#define BK 64
#define NTHREADS 256                   // 8 warps, 2x4, 64x32 warp tiles
#define STAGES 3
#define PERSIST_CTAS 296               // 2 CTAs/SM x 148 SMs

// smem pitch in fp16: 64 k + 8 pad = 72 (144B rows; ldmatrix conflict-free)
#define PA 72
#define SBUFA (128 * PA)
#define SBUFB (128 * PA)
#define STAGE_H (SBUFA + SBUFB)
#define SMEM_BYTES_G (STAGES * STAGE_H * 2)   // 110,592 B -> 2 CTAs/SM

// Epilogue tags
#define EPI_GATE     0
#define EPI_SCALE    1
#define EPI_ADD      2
#define EPI_GELU     3
#define EPI_BIAS_RES 4

// ---------------------------------------------------------------------------
// Scratch (device globals: allocation-free rule)
// ---------------------------------------------------------------------------
__device__ __half g_fusedh [(size_t)NTOK * DIM];         // gate out, then PV residual src
__device__ __half g_attnfh [(size_t)NTOK * DIM];         // PV out (attn+res, fp16)
__device__ __half g_attnh  [(size_t)BATCH * SEQ * SEQ];  // logits then weights
__device__ __half g_qh     [(size_t)NTOK * DIM];
__device__ __half g_hh     [(size_t)NTOK * 2 * DIM];
__device__ __half g_yh     [(size_t)NTOK * DIM];         // FFN2 out (fp16)
__device__ __half g_noiseh [(size_t)NTOK * DIM];
__device__ __half g_condh  [(size_t)NTOK * DIM];
__device__ __half g_xh     [(size_t)NTOK * DIM];         // X fp16 [S,D]
__device__ __half g_xth    [(size_t)BATCH * DIM * SEQ];  // X^T fp16 [D,S]
__device__ __half g_wgth   [(size_t)DIM * 2 * DIM];
__device__ __half g_w1th   [(size_t)2 * DIM * DIM];
__device__ __half g_w2th   [(size_t)DIM * 2 * DIM];

// ---------------------------------------------------------------------------
// PTX helpers
// ---------------------------------------------------------------------------
__device__ __forceinline__ uint32_t smem_u32(const void* p) {
    uint32_t a;
    asm("{ .reg .u64 t; cvta.to.shared.u64 t, %1; cvt.u32.u64 %0, t; }" : "=r"(a) : "l"(p));
    return a;
}
__device__ __forceinline__ void cp16(uint32_t saddr, const void* gaddr) {
    asm volatile("cp.async.cg.shared.global [%0], [%1], 16;" :: "r"(saddr), "l"(gaddr));
}
__device__ __forceinline__ void cp_commit() {
    asm volatile("cp.async.commit_group;" ::: "memory");
}
template<int N>
__device__ __forceinline__ void cp_wait() {
    asm volatile("cp.async.wait_group %0;" :: "n"(N) : "memory");
}
__device__ __forceinline__ void mma_f16(float* c, uint32_t a0, uint32_t a1,
                                        uint32_t a2, uint32_t a3,
                                        uint32_t b0, uint32_t b1) {
    asm volatile("mma.sync.aligned.m16n8k16.row.col.f32.f16.f16.f32 "
                 "{%0,%1,%2,%3}, {%4,%5,%6,%7}, {%8,%9}, {%0,%1,%2,%3};"
                 : "+f"(c[0]), "+f"(c[1]), "+f"(c[2]), "+f"(c[3])
                 : "r"(a0), "r"(a1), "r"(a2), "r"(a3), "r"(b0), "r"(b1));
}
__device__ __forceinline__ void ldsm4(uint32_t& r0, uint32_t& r1, uint32_t& r2,
                                      uint32_t& r3, uint32_t addr) {
    asm volatile("ldmatrix.sync.aligned.m8n8.x4.shared.b16 {%0,%1,%2,%3}, [%4];"
                 : "=r"(r0), "=r"(r1), "=r"(r2), "=r"(r3) : "r"(addr));
}

// ---------------------------------------------------------------------------
// Persistent fp16 tensor-core GEMM: C[M,N] = A[M,K] * B^T, B [N,K] K-contig.
// 128x128x64 CTA tile, 8 warps (2x4), 64x32 warp tiles, ldmatrix fragments,
// 3-stage cp.async ring (group-aligned via empty commits), 1 barrier/K-iter.
// Each CTA loops over tiles: t -> (bn, bm, z).  fp32 accumulate, fp16 out.
// SPLITA: A cols [0,512) from A, [512,1024) from A2 (virtual concat).
// ---------------------------------------------------------------------------
template<int EPI, bool SPLITA>
__global__ void __launch_bounds__(NTHREADS, 2)
gemm_mma(const __half* __restrict__ Ab, const __half* __restrict__ A2b,
         const __half* __restrict__ Bb,
         __half* __restrict__ Chb,
         int K, int lda, int ldb, int ldc,
         size_t strA, size_t strB, size_t strC,
         const float* __restrict__ bias,
         const __half* __restrict__ hres0b,
         const __half* __restrict__ hres1b,
         float scale,
         int n_bn, int n_bm, int n_z)
{
    extern __shared__ __half hsm[];

    const int tid  = threadIdx.x;
    const int wid  = tid >> 5;
    const int lane = tid & 31;
    const int warp_m = wid & 1;
    const int warp_n = wid >> 1;
    const int g  = lane >> 2;
    const int tg = lane & 3;
    const int quad  = lane >> 3;
    const int rowin = lane & 7;

    const int a_row = (quad & 1) * 8 + rowin;
    const int a_col = (quad >> 1) * 8;
    const int b_row = (quad >> 1) * 8 + rowin;
    const int b_col = (quad & 1) * 8;

    const uint32_t smB = smem_u32(hsm);
    const int nit = K / BK;
    const int total = n_bn * n_bm * n_z;

    for (int t = blockIdx.x; t < total; t += gridDim.x) {
        const int bn = (t % n_bn) * BN;
        const int bm = ((t / n_bn) % n_bm) * BM;
        const int z  = t / (n_bn * n_bm);

        const __half* A  = Ab + (size_t)z * strA;
        const __half* B  = Bb + (size_t)z * strB;
        __half* Ch       = Chb + (size_t)z * strC;
        const __half* hres0 = hres0b ? hres0b + (size_t)z * strC : nullptr;
        const __half* hres1 = hres1b ? hres1b + (size_t)z * strC : nullptr;

        float acc[4][4][4];
        #pragma unroll
        for (int i = 0; i < 4; i++)
            #pragma unroll
            for (int j = 0; j < 4; j++)
                #pragma unroll
                for (int e = 0; e < 4; e++) acc[i][j][e] = 0.f;

        auto prefetch = [&](int it) {
            const int kk = it * BK;
            const int st = it % STAGES;
            const uint32_t sa = smB + (uint32_t)(st * STAGE_H) * 2u;
            const uint32_t sb = sa + (uint32_t)SBUFA * 2u;
            #pragma unroll
            for (int tt = 0; tt < 4; tt++) {
                int id = tid + tt * NTHREADS;
                int r  = id >> 3;
                int c8 = id & 7;
                int col = kk + c8 * 8;
                const __half* src;
                if (SPLITA) {
                    src = (col < DIM) ? (A  + (size_t)(bm + r) * DIM + col)
                                      : (A2b + (size_t)(bm + r) * DIM + (col - DIM));
                } else {
                    src = A + (size_t)(bm + r) * lda + col;
                }
                cp16(sa + (uint32_t)(r * PA + c8 * 8) * 2u, src);
            }
            #pragma unroll
            for (int tt = 0; tt < 4; tt++) {
                int id = tid + tt * NTHREADS;
                int r  = id >> 3;
                int c8 = id & 7;
                cp16(sb + (uint32_t)(r * PA + c8 * 8) * 2u,
                     B + (size_t)(bn + r) * ldb + kk + c8 * 8);
            }
            cp_commit();
        };

        prefetch(0);
        prefetch(1);

        #pragma unroll 1
        for (int it = 0; it < nit; it++) {
            cp_wait<1>();          // group 'it' retired (empty commits keep alignment)
            __syncthreads();
            if (it + 2 < nit) prefetch(it + 2);
            else cp_commit();      // empty group: keeps wait<1> semantics exact

            const int st = it % STAGES;
            const uint32_t sa = smB + (uint32_t)(st * STAGE_H) * 2u;
            const uint32_t sb = sa + (uint32_t)SBUFA * 2u;

            #pragma unroll
            for (int ks = 0; ks < 4; ks++) {
                const int kc = ks * 16;
                uint32_t af[4][4];
                #pragma unroll
                for (int mt = 0; mt < 4; mt++) {
                    int m = warp_m * 64 + mt * 16;
                    uint32_t addr = sa + (uint32_t)((m + a_row) * PA + kc + a_col) * 2u;
                    ldsm4(af[mt][0], af[mt][1], af[mt][2], af[mt][3], addr);
                }
                uint32_t bf[4][2];
                #pragma unroll
                for (int np = 0; np < 2; np++) {
                    int n = warp_n * 32 + np * 16;
                    uint32_t addr = sb + (uint32_t)((n + b_row) * PA + kc + b_col) * 2u;
                    ldsm4(bf[np*2][0], bf[np*2][1], bf[np*2+1][0], bf[np*2+1][1], addr);
                }
                #pragma unroll
                for (int mt = 0; mt < 4; mt++)
                    #pragma unroll
                    for (int nt = 0; nt < 4; nt++)
                        mma_f16(acc[mt][nt], af[mt][0], af[mt][1], af[mt][2], af[mt][3],
                                bf[nt][0], bf[nt][1]);
            }
        }

        // ---- epilogue (all outputs fp16) ----
        #pragma unroll
        for (int mt = 0; mt < 4; mt++) {
            #pragma unroll
            for (int nt = 0; nt < 4; nt++) {
                int r0 = bm + warp_m * 64 + mt * 16 + g;
                int cc = bn + warp_n * 32 + nt * 8 + tg * 2;
                #pragma unroll
                for (int half = 0; half < 2; half++) {
                    int r = r0 + half * 8;
                    float v0 = acc[mt][nt][half * 2 + 0];
                    float v1 = acc[mt][nt][half * 2 + 1];
                    size_t gix = (size_t)r * ldc + cc;
                    float o0, o1;
                    if (EPI == EPI_GATE) {
                        float2 n2 = __half22float2(*reinterpret_cast<const __half2*>(&hres0[gix]));
                        float2 c2 = __half22float2(*reinterpret_cast<const __half2*>(&hres1[gix]));
                        float gt0 = 1.f / (1.f + __expf(-(v0 + bias[cc])));
                        float gt1 = 1.f / (1.f + __expf(-(v1 + bias[cc + 1])));
                        o0 = gt0 * n2.x + (1.f - gt0) * c2.x;
                        o1 = gt1 * n2.y + (1.f - gt1) * c2.y;
                    } else if (EPI == EPI_SCALE) {
                        o0 = v0 * scale; o1 = v1 * scale;
                    } else if (EPI == EPI_ADD) {
                        float2 r2 = __half22float2(*reinterpret_cast<const __half2*>(&hres0[gix]));
                        o0 = v0 + r2.x; o1 = v1 + r2.y;
                    } else if (EPI == EPI_GELU) {
                        float x0 = v0 + bias[cc], x1 = v1 + bias[cc + 1];
                        o0 = 0.5f * x0 * (1.f + erff(x0 * 0.70710678118654752440f));
                        o1 = 0.5f * x1 * (1.f + erff(x1 * 0.70710678118654752440f));
                    } else { // EPI_BIAS_RES
                        float2 r2 = __half22float2(*reinterpret_cast<const __half2*>(&hres0[gix]));
                        o0 = v0 + bias[cc]     + r2.x;
                        o1 = v1 + bias[cc + 1] + r2.y;
                    }
                    *reinterpret_cast<__half2*>(&Ch[gix]) = __floats2half2_rn(o0, o1);
                }
            }
        }
        __syncthreads();   // protect smem stages before next tile's prefetch
    }
}

// ---------------------------------------------------------------------------
// fp32 -> fp16 convert of TWO arrays in one pass
// ---------------------------------------------------------------------------
__global__ void __launch_bounds__(256)
convert2_h(const float* __restrict__ a, __half* __restrict__ oa,
           const float* __restrict__ b, __half* __restrict__ ob)
{
    size_t i4 = (size_t)blockIdx.x * 256 + threadIdx.x;
    float4 va = reinterpret_cast<const float4*>(a)[i4];
    float4 vb = reinterpret_cast<const float4*>(b)[i4];
    reinterpret_cast<__half2*>(oa)[i4 * 2]     = __floats2half2_rn(va.x, va.y);
    reinterpret_cast<__half2*>(oa)[i4 * 2 + 1] = __floats2half2_rn(va.z, va.w);
    reinterpret_cast<__half2*>(ob)[i4 * 2]     = __floats2half2_rn(vb.x, vb.y);
    reinterpret_cast<__half2*>(ob)[i4 * 2 + 1] = __floats2half2_rn(vb.z, vb.w);
}

// ---------------------------------------------------------------------------
// Tiled transpose + convert; optionally also writes the straight fp16 copy.
// ---------------------------------------------------------------------------
__global__ void __launch_bounds__(256)
transpose_h(const float* __restrict__ in, __half* __restrict__ out_t,
            __half* __restrict__ out_c, int R, int C)
{
    __shared__ float t[32][33];
    in    += (size_t)blockIdx.z * R * C;
    out_t += (size_t)blockIdx.z * R * C;
    if (out_c) out_c += (size_t)blockIdx.z * R * C;
    int r0 = blockIdx.y * 32, c0 = blockIdx.x * 32;
    int x = threadIdx.x, y = threadIdx.y;
    #pragma unroll
    for (int i = 0; i < 32; i += 8) {
        float v = in[(size_t)(r0 + y + i) * C + c0 + x];
        t[y + i][x] = v;
        if (out_c) out_c[(size_t)(r0 + y + i) * C + c0 + x] = __float2half_rn(v);
    }
    __syncthreads();
    #pragma unroll
    for (int i = 0; i < 32; i += 8)
        out_t[(size_t)(c0 + y + i) * R + r0 + x] = __float2half_rn(t[x][y + i]);
}

// ---------------------------------------------------------------------------
// Warp helpers
// ---------------------------------------------------------------------------
__device__ __forceinline__ float warpMax(float v) {
    #pragma unroll
    for (int o = 16; o > 0; o >>= 1) v = fmaxf(v, __shfl_xor_sync(0xffffffffu, v, o));
    return v;
}
__device__ __forceinline__ float warpSum(float v) {
    #pragma unroll
    for (int o = 16; o > 0; o >>= 1) v += __shfl_xor_sync(0xffffffffu, v, o);
    return v;
}

// ---------------------------------------------------------------------------
// Row softmax over 2048 fp16 logits, in place (fp32 math, fast exp)
// ---------------------------------------------------------------------------
__global__ void __launch_bounds__(256)
softmax_kernel(__half* __restrict__ S)
{
    __half* p = S + (size_t)blockIdx.x * SEQ;
    const int tid  = threadIdx.x;
    const int lane = tid & 31;
    const int wid  = tid >> 5;
    __shared__ float sh[8];

    __half2 hv[4];
    *reinterpret_cast<float4*>(hv) = *reinterpret_cast<const float4*>(&p[tid * 8]);
    float v[8];
    #pragma unroll
    for (int i = 0; i < 4; i++) {
        float2 f = __half22float2(hv[i]);
        v[i*2] = f.x; v[i*2+1] = f.y;
    }

    float m = v[0];
    #pragma unroll
    for (int i = 1; i < 8; i++) m = fmaxf(m, v[i]);
    m = warpMax(m);
    if (lane == 0) sh[wid] = m;
    __syncthreads();
    m = sh[0];
    #pragma unroll
    for (int w = 1; w < 8; w++) m = fmaxf(m, sh[w]);
    __syncthreads();

    float s = 0.f;
    #pragma unroll
    for (int i = 0; i < 8; i++) { v[i] = __expf(v[i] - m); s += v[i]; }
    s = warpSum(s);
    if (lane == 0) sh[wid] = s;
    __syncthreads();
    float tot = sh[0];
    #pragma unroll
    for (int w = 1; w < 8; w++) tot += sh[w];
    float inv = 1.f / tot;

    #pragma unroll
    for (int i = 0; i < 4; i++)
        hv[i] = __floats2half2_rn(v[i*2] * inv, v[i*2+1] * inv);
    *reinterpret_cast<float4*>(&p[tid * 8]) = *reinterpret_cast<float4*>(hv);
}

// ---------------------------------------------------------------------------
// LayerNorm over last dim (512), fp16 input; fp32 and/or fp16 outputs.
// ---------------------------------------------------------------------------
__global__ void __launch_bounds__(128)
layernorm_h(const __half* __restrict__ in, float* __restrict__ out,
            __half* __restrict__ out_h,
            const float* __restrict__ gamma, const float* __restrict__ beta)
{
    const size_t base = (size_t)blockIdx.x * DIM;
    const int tid  = threadIdx.x;
    const int lane = tid & 31;
    const int wid  = tid >> 5;
    __shared__ float shs[4], shq[4];

    __half2 h0 = *reinterpret_cast<const __half2*>(&in[base + tid * 4]);
    __half2 h1 = *reinterpret_cast<const __half2*>(&in[base + tid * 4 + 2]);
    float2 f0 = __half22float2(h0);
    float2 f1 = __half22float2(h1);
    float x0 = f0.x, x1 = f0.y, x2 = f1.x, x3 = f1.y;

    float s  = x0 + x1 + x2 + x3;
    float ss = x0 * x0 + x1 * x1 + x2 * x2 + x3 * x3;
    s  = warpSum(s);
    ss = warpSum(ss);
    if (lane == 0) { shs[wid] = s; shq[wid] = ss; }
    __syncthreads();
    float sum = shs[0] + shs[1] + shs[2] + shs[3];
    float sq  = shq[0] + shq[1] + shq[2] + shq[3];
    float mu  = sum * (1.f / DIM);
    float var = sq * (1.f / DIM) - mu * mu;
    float rs  = rsqrtf(var + 1e-5f);

    float4 gm = *reinterpret_cast<const float4*>(&gamma[tid * 4]);
    float4 bt = *reinterpret_cast<const float4*>(&beta[tid * 4]);
    float o0 = (x0 - mu) * rs * gm.x + bt.x;
    float o1 = (x1 - mu) * rs * gm.y + bt.y;
    float o2 = (x2 - mu) * rs * gm.z + bt.z;
    float o3 = (x3 - mu) * rs * gm.w + bt.w;
    if (out) {
        float4 o = make_float4(o0, o1, o2, o3);
        *reinterpret_cast<float4*>(&out[base + tid * 4]) = o;
    }
    if (out_h) {
        *reinterpret_cast<__half2*>(&out_h[base + tid * 4])     = __floats2half2_rn(o0, o1);
        *reinterpret_cast<__half2*>(&out_h[base + tid * 4 + 2]) = __floats2half2_rn(o2, o3);
    }
}

// ---------------------------------------------------------------------------
// Launch
// ---------------------------------------------------------------------------
static inline int pgrid(int total) { return total < PERSIST_CTAS ? total : PERSIST_CTAS; }

extern "C" void kernel_launch(void* const* d_in, const int* in_sizes, int n_in,
                              void* d_out, int out_size)
{
    const float* Noise = (const float*)d_in[0];
    const float* X     = (const float*)d_in[1];
    const float* cond  = (const float*)d_in[2];
    const float* Wg    = (const float*)d_in[3];
    const float* bg    = (const float*)d_in[4];
    const float* W1    = (const float*)d_in[5];
    const float* b1    = (const float*)d_in[6];
    const float* W2    = (const float*)d_in[7];
    const float* b2    = (const float*)d_in[8];
    const float* g1    = (const float*)d_in[9];
    const float* be1   = (const float*)d_in[10];
    const float* g2    = (const float*)d_in[11];
    const float* be2   = (const float*)d_in[12];
    float* out = (float*)d_out;

    __half *fusedh, *attnfh, *attnh, *qh, *hh, *yh, *noiseh, *condh, *xh, *xth, *wgth, *w1th, *w2th;
    cudaGetSymbolAddress((void**)&fusedh, g_fusedh);
    cudaGetSymbolAddress((void**)&attnfh, g_attnfh);
    cudaGetSymbolAddress((void**)&attnh,  g_attnh);
    cudaGetSymbolAddress((void**)&qh,     g_qh);
    cudaGetSymbolAddress((void**)&hh,     g_hh);
    cudaGetSymbolAddress((void**)&yh,     g_yh);
    cudaGetSymbolAddress((void**)&noiseh, g_noiseh);
    cudaGetSymbolAddress((void**)&condh,  g_condh);
    cudaGetSymbolAddress((void**)&xh,     g_xh);
    cudaGetSymbolAddress((void**)&xth,    g_xth);
    cudaGetSymbolAddress((void**)&wgth,   g_wgth);
    cudaGetSymbolAddress((void**)&w1th,   g_w1th);
    cudaGetSymbolAddress((void**)&w2th,   g_w2th);

    cudaFuncSetAttribute(gemm_mma<EPI_GATE, true>,      cudaFuncAttributeMaxDynamicSharedMemorySize, SMEM_BYTES_G);
    cudaFuncSetAttribute(gemm_mma<EPI_SCALE, false>,    cudaFuncAttributeMaxDynamicSharedMemorySize, SMEM_BYTES_G);
    cudaFuncSetAttribute(gemm_mma<EPI_ADD, false>,      cudaFuncAttributeMaxDynamicSharedMemorySize, SMEM_BYTES_G);
    cudaFuncSetAttribute(gemm_mma<EPI_GELU, false>,     cudaFuncAttributeMaxDynamicSharedMemorySize, SMEM_BYTES_G);
    cudaFuncSetAttribute(gemm_mma<EPI_BIAS_RES, false>, cudaFuncAttributeMaxDynamicSharedMemorySize, SMEM_BYTES_G);

    const float scale = 0.04419417382415922f;  // 1/sqrt(512)
    const int NEL = NTOK * DIM;

    // 0. fp16 conversions + transposes
    convert2_h<<<NEL / 4 / 256, 256>>>(Noise, noiseh, cond, condh);
    transpose_h<<<dim3(DIM / 32, 2 * DIM / 32, 1), dim3(32, 8)>>>(Wg, wgth, nullptr, 2 * DIM, DIM);
    transpose_h<<<dim3(2 * DIM / 32, DIM / 32, 1), dim3(32, 8)>>>(W1, w1th, nullptr, DIM, 2 * DIM);
    transpose_h<<<dim3(DIM / 32, 2 * DIM / 32, 1), dim3(32, 8)>>>(W2, w2th, nullptr, 2 * DIM, DIM);
    transpose_h<<<dim3(DIM / 32, SEQ / 32, BATCH), dim3(32, 8)>>>(X, xth, xh, SEQ, DIM);

    // 1. gate+fuse -> fusedh
    gemm_mma<EPI_GATE, true><<<pgrid(4 * 128), NTHREADS, SMEM_BYTES_G>>>(
        noiseh, condh, wgth, fusedh,
        2 * DIM, 2 * DIM, 2 * DIM, DIM,
        0, 0, 0, bg, noiseh, condh, 0.f,
        DIM / BN, NTOK / BM, 1);

    // 2. logits = fused @ X^T * scale -> attnh
    gemm_mma<EPI_SCALE, false><<<pgrid(16 * 16 * 8), NTHREADS, SMEM_BYTES_G>>>(
        fusedh, nullptr, xh, attnh,
        DIM, DIM, DIM, SEQ,
        (size_t)SEQ * DIM, (size_t)SEQ * DIM, (size_t)SEQ * SEQ,
        nullptr, nullptr, nullptr, scale,
        SEQ / BN, SEQ / BM, BATCH);

    // 3. softmax in place
    softmax_kernel<<<NTOK, 256>>>(attnh);

    // 4. attnfh = attn @ X + fusedh
    gemm_mma<EPI_ADD, false><<<pgrid(4 * 16 * 8), NTHREADS, SMEM_BYTES_G>>>(
        attnh, nullptr, xth, attnfh,
        SEQ, SEQ, SEQ, DIM,
        (size_t)SEQ * SEQ, (size_t)DIM * SEQ, (size_t)SEQ * DIM,
        nullptr, fusedh, nullptr, 0.f,
        DIM / BN, SEQ / BM, BATCH);

    // 5. qh = LN1(attnfh)
    layernorm_h<<<NTOK, 128>>>(attnfh, nullptr, qh, g1, be1);

    // 6. hh = gelu(qh @ W1 + b1)
    gemm_mma<EPI_GELU, false><<<pgrid(8 * 128), NTHREADS, SMEM_BYTES_G>>>(
        qh, nullptr, w1th, hh,
        DIM, DIM, DIM, 2 * DIM,
        0, 0, 0, b1, nullptr, nullptr, 0.f,
        2 * DIM / BN, NTOK / BM, 1);

    // 7. yh = hh @ W2 + b2 + qh
    gemm_mma<EPI_BIAS_RES, false><<<pgrid(4 * 128), NTHREADS, SMEM_BYTES_G>>>(
        hh, nullptr, w2th, yh,
        2 * DIM, 2 * DIM, 2 * DIM, DIM,
        0, 0, 0, b2, qh, nullptr, 0.f,
        DIM / BN, NTOK / BM, 1);

    // 8. out = LN2(yh)
    layernorm_h<<<NTOK, 128>>>(yh, out, nullptr, g2, be2);
}

// round 17
// speedup vs baseline: 1.5483x; 1.5483x over previous
#include <cuda_runtime.h>
#include <cuda_fp16.h>
#include <math.h>
#include <stdint.h>

// ---------------------------------------------------------------------------
// Problem constants
// ---------------------------------------------------------------------------
#define BATCH   8
#define SEQ     2048
#define DIM     512
#define NTOK    (BATCH * SEQ)          // 16384

// GEMM tiling (mma.sync m16n8k16 fp16) — proven R12 shape
#define BM 128
#define BN 128
#define BK 64
#define NTHREADS 256                   // 8 warps, 2x4, 64x32 warp tiles
#define STAGES 3

// smem pitch in fp16: 64 k + 8 pad = 72 (144B rows; ldmatrix conflict-free)
#define PA 72
#define SBUFA (128 * PA)
#define SBUFB (128 * PA)
#define STAGE_H (SBUFA + SBUFB)
#define SMEM_BYTES_G (STAGES * STAGE_H * 2)   // 110,592 B -> 2 CTAs/SM

// Epilogue tags
#define EPI_GATE     0
#define EPI_SCALE    1
#define EPI_ADD      2
#define EPI_GELU     3
#define EPI_BIAS_RES 4

// ---------------------------------------------------------------------------
// Scratch (device globals: allocation-free rule)
// ---------------------------------------------------------------------------
__device__ __half g_fusedh [(size_t)NTOK * DIM];         // gate out / PV residual
__device__ __half g_attnfh [(size_t)NTOK * DIM];         // PV out (attn+res)
__device__ __half g_attnh  [(size_t)BATCH * SEQ * SEQ];  // logits then weights
__device__ __half g_qh     [(size_t)NTOK * DIM];
__device__ __half g_hh     [(size_t)NTOK * 2 * DIM];
__device__ __half g_yh     [(size_t)NTOK * DIM];         // FFN2 out
__device__ __half g_noiseh [(size_t)NTOK * DIM];
__device__ __half g_condh  [(size_t)NTOK * DIM];
__device__ __half g_xh     [(size_t)NTOK * DIM];         // X fp16 [S,D]
__device__ __half g_xth    [(size_t)BATCH * DIM * SEQ];  // X^T fp16 [D,S]
__device__ __half g_wgth   [(size_t)DIM * 2 * DIM];
__device__ __half g_w1th   [(size_t)2 * DIM * DIM];
__device__ __half g_w2th   [(size_t)DIM * 2 * DIM];

// ---------------------------------------------------------------------------
// PTX helpers
// ---------------------------------------------------------------------------
__device__ __forceinline__ uint32_t smem_u32(const void* p) {
    uint32_t a;
    asm("{ .reg .u64 t; cvta.to.shared.u64 t, %1; cvt.u32.u64 %0, t; }" : "=r"(a) : "l"(p));
    return a;
}
__device__ __forceinline__ void cp16(uint32_t saddr, const void* gaddr) {
    asm volatile("cp.async.cg.shared.global [%0], [%1], 16;" :: "r"(saddr), "l"(gaddr));
}
__device__ __forceinline__ void cp_commit() {
    asm volatile("cp.async.commit_group;" ::: "memory");
}
template<int N>
__device__ __forceinline__ void cp_wait() {
    asm volatile("cp.async.wait_group %0;" :: "n"(N) : "memory");
}
__device__ __forceinline__ void mma_f16(float* c, uint32_t a0, uint32_t a1,
                                        uint32_t a2, uint32_t a3,
                                        uint32_t b0, uint32_t b1) {
    asm volatile("mma.sync.aligned.m16n8k16.row.col.f32.f16.f16.f32 "
                 "{%0,%1,%2,%3}, {%4,%5,%6,%7}, {%8,%9}, {%0,%1,%2,%3};"
                 : "+f"(c[0]), "+f"(c[1]), "+f"(c[2]), "+f"(c[3])
                 : "r"(a0), "r"(a1), "r"(a2), "r"(a3), "r"(b0), "r"(b1));
}
__device__ __forceinline__ void ldsm4(uint32_t& r0, uint32_t& r1, uint32_t& r2,
                                      uint32_t& r3, uint32_t addr) {
    asm volatile("ldmatrix.sync.aligned.m8n8.x4.shared.b16 {%0,%1,%2,%3}, [%4];"
                 : "=r"(r0), "=r"(r1), "=r"(r2), "=r"(r3) : "r"(addr));
}

// ---------------------------------------------------------------------------
// fp16 tensor-core GEMM: C[M,N] = A[M,K] * B^T, A [M,K], B [N,K] (K-contig).
// 128x128x64 CTA tile, 8 warps (2x4), 64x32 warp tiles, ldmatrix fragments,
// 3-stage cp.async ring, 1 barrier per K=64 iter.  fp32 accumulate, fp16 out.
// SPLITA: A cols [0,512) from A, [512,1024) from A2 (virtual concat).
// ---------------------------------------------------------------------------
template<int EPI, bool SPLITA>
__global__ void __launch_bounds__(NTHREADS, 2)
gemm_mma(const __half* __restrict__ A, const __half* __restrict__ A2,
         const __half* __restrict__ B,
         __half* __restrict__ Ch,
         int K, int lda, int ldb, int ldc,
         size_t strA, size_t strB, size_t strC,
         const float* __restrict__ bias,
         const __half* __restrict__ hres0,
         const __half* __restrict__ hres1,
         float scale)
{
    extern __shared__ __half hsm[];

    const int z = blockIdx.z;
    A += (size_t)z * strA;
    B += (size_t)z * strB;
    Ch += (size_t)z * strC;
    if (hres0) hres0 += (size_t)z * strC;
    if (hres1) hres1 += (size_t)z * strC;

    const int bm   = blockIdx.y * BM;
    const int bn   = blockIdx.x * BN;
    const int tid  = threadIdx.x;
    const int wid  = tid >> 5;
    const int lane = tid & 31;
    const int warp_m = wid & 1;        // 0..1 -> 64 rows
    const int warp_n = wid >> 1;       // 0..3 -> 32 cols
    const int g  = lane >> 2;          // 0..7
    const int tg = lane & 3;           // 0..3
    const int quad  = lane >> 3;       // 0..3
    const int rowin = lane & 7;        // 0..7

    const int a_row = (quad & 1) * 8 + rowin;
    const int a_col = (quad >> 1) * 8;
    const int b_row = (quad >> 1) * 8 + rowin;
    const int b_col = (quad & 1) * 8;

    const uint32_t smB = smem_u32(hsm);

    float acc[4][4][4];
    #pragma unroll
    for (int i = 0; i < 4; i++)
        #pragma unroll
        for (int j = 0; j < 4; j++)
            #pragma unroll
            for (int e = 0; e < 4; e++) acc[i][j][e] = 0.f;

    const int nit = K / BK;

    auto prefetch = [&](int it) {
        const int kk = it * BK;
        const int st = it % STAGES;
        const uint32_t sa = smB + (uint32_t)(st * STAGE_H) * 2u;
        const uint32_t sb = sa + (uint32_t)SBUFA * 2u;
        #pragma unroll
        for (int t = 0; t < 4; t++) {
            int id = tid + t * NTHREADS;       // 0..1023
            int r  = id >> 3;                  // 0..127
            int c8 = id & 7;
            int col = kk + c8 * 8;
            const __half* src;
            if (SPLITA) {
                src = (col < DIM) ? (A  + (size_t)(bm + r) * DIM + col)
                                  : (A2 + (size_t)(bm + r) * DIM + (col - DIM));
            } else {
                src = A + (size_t)(bm + r) * lda + col;
            }
            cp16(sa + (uint32_t)(r * PA + c8 * 8) * 2u, src);
        }
        #pragma unroll
        for (int t = 0; t < 4; t++) {
            int id = tid + t * NTHREADS;
            int r  = id >> 3;
            int c8 = id & 7;
            cp16(sb + (uint32_t)(r * PA + c8 * 8) * 2u,
                 B + (size_t)(bn + r) * ldb + kk + c8 * 8);
        }
        cp_commit();
    };

    prefetch(0);
    prefetch(1);

    #pragma unroll 1
    for (int it = 0; it < nit; it++) {
        cp_wait<1>();
        __syncthreads();
        if (it + 2 < nit) prefetch(it + 2);

        const int st = it % STAGES;
        const uint32_t sa = smB + (uint32_t)(st * STAGE_H) * 2u;
        const uint32_t sb = sa + (uint32_t)SBUFA * 2u;

        #pragma unroll
        for (int ks = 0; ks < 4; ks++) {
            const int kc = ks * 16;
            uint32_t af[4][4];
            #pragma unroll
            for (int mt = 0; mt < 4; mt++) {
                int m = warp_m * 64 + mt * 16;
                uint32_t addr = sa + (uint32_t)((m + a_row) * PA + kc + a_col) * 2u;
                ldsm4(af[mt][0], af[mt][1], af[mt][2], af[mt][3], addr);
            }
            uint32_t bf[4][2];
            #pragma unroll
            for (int np = 0; np < 2; np++) {
                int n = warp_n * 32 + np * 16;
                uint32_t addr = sb + (uint32_t)((n + b_row) * PA + kc + b_col) * 2u;
                ldsm4(bf[np*2][0], bf[np*2][1], bf[np*2+1][0], bf[np*2+1][1], addr);
            }
            #pragma unroll
            for (int mt = 0; mt < 4; mt++)
                #pragma unroll
                for (int nt = 0; nt < 4; nt++)
                    mma_f16(acc[mt][nt], af[mt][0], af[mt][1], af[mt][2], af[mt][3],
                            bf[nt][0], bf[nt][1]);
        }
    }

    // ---- epilogue (fp16 out) ----
    #pragma unroll
    for (int mt = 0; mt < 4; mt++) {
        #pragma unroll
        for (int nt = 0; nt < 4; nt++) {
            int r0 = bm + warp_m * 64 + mt * 16 + g;
            int cc = bn + warp_n * 32 + nt * 8 + tg * 2;
            #pragma unroll
            for (int half = 0; half < 2; half++) {
                int r = r0 + half * 8;
                float v0 = acc[mt][nt][half * 2 + 0];
                float v1 = acc[mt][nt][half * 2 + 1];
                size_t gix = (size_t)r * ldc + cc;
                float o0, o1;
                if (EPI == EPI_GATE) {
                    float2 n2 = __half22float2(*reinterpret_cast<const __half2*>(&hres0[gix]));
                    float2 c2 = __half22float2(*reinterpret_cast<const __half2*>(&hres1[gix]));
                    float gt0 = 1.f / (1.f + __expf(-(v0 + bias[cc])));
                    float gt1 = 1.f / (1.f + __expf(-(v1 + bias[cc + 1])));
                    o0 = gt0 * n2.x + (1.f - gt0) * c2.x;
                    o1 = gt1 * n2.y + (1.f - gt1) * c2.y;
                } else if (EPI == EPI_SCALE) {
                    o0 = v0 * scale; o1 = v1 * scale;
                } else if (EPI == EPI_ADD) {
                    float2 r2 = __half22float2(*reinterpret_cast<const __half2*>(&hres0[gix]));
                    o0 = v0 + r2.x; o1 = v1 + r2.y;
                } else if (EPI == EPI_GELU) {
                    float x0 = v0 + bias[cc], x1 = v1 + bias[cc + 1];
                    o0 = 0.5f * x0 * (1.f + erff(x0 * 0.70710678118654752440f));
                    o1 = 0.5f * x1 * (1.f + erff(x1 * 0.70710678118654752440f));
                } else { // EPI_BIAS_RES
                    float2 r2 = __half22float2(*reinterpret_cast<const __half2*>(&hres0[gix]));
                    o0 = v0 + bias[cc]     + r2.x;
                    o1 = v1 + bias[cc + 1] + r2.y;
                }
                *reinterpret_cast<__half2*>(&Ch[gix]) = __floats2half2_rn(o0, o1);
            }
        }
    }
}

// ---------------------------------------------------------------------------
// fp32 -> fp16 convert of TWO arrays in one pass
// ---------------------------------------------------------------------------
__global__ void __launch_bounds__(256)
convert2_h(const float* __restrict__ a, __half* __restrict__ oa,
           const float* __restrict__ b, __half* __restrict__ ob)
{
    size_t i4 = (size_t)blockIdx.x * 256 + threadIdx.x;
    float4 va = reinterpret_cast<const float4*>(a)[i4];
    float4 vb = reinterpret_cast<const float4*>(b)[i4];
    reinterpret_cast<__half2*>(oa)[i4 * 2]     = __floats2half2_rn(va.x, va.y);
    reinterpret_cast<__half2*>(oa)[i4 * 2 + 1] = __floats2half2_rn(va.z, va.w);
    reinterpret_cast<__half2*>(ob)[i4 * 2]     = __floats2half2_rn(vb.x, vb.y);
    reinterpret_cast<__half2*>(ob)[i4 * 2 + 1] = __floats2half2_rn(vb.z, vb.w);
}

// ---------------------------------------------------------------------------
// Tiled transpose + convert; optionally also writes the straight fp16 copy.
// ---------------------------------------------------------------------------
__global__ void __launch_bounds__(256)
transpose_h(const float* __restrict__ in, __half* __restrict__ out_t,
            __half* __restrict__ out_c, int R, int C)
{
    __shared__ float t[32][33];
    in    += (size_t)blockIdx.z * R * C;
    out_t += (size_t)blockIdx.z * R * C;
    if (out_c) out_c += (size_t)blockIdx.z * R * C;
    int r0 = blockIdx.y * 32, c0 = blockIdx.x * 32;
    int x = threadIdx.x, y = threadIdx.y;
    #pragma unroll
    for (int i = 0; i < 32; i += 8) {
        float v = in[(size_t)(r0 + y + i) * C + c0 + x];
        t[y + i][x] = v;
        if (out_c) out_c[(size_t)(r0 + y + i) * C + c0 + x] = __float2half_rn(v);
    }
    __syncthreads();
    #pragma unroll
    for (int i = 0; i < 32; i += 8)
        out_t[(size_t)(c0 + y + i) * R + r0 + x] = __float2half_rn(t[x][y + i]);
}

// ---------------------------------------------------------------------------
// Warp helpers
// ---------------------------------------------------------------------------
__device__ __forceinline__ float warpMax(float v) {
    #pragma unroll
    for (int o = 16; o > 0; o >>= 1) v = fmaxf(v, __shfl_xor_sync(0xffffffffu, v, o));
    return v;
}
__device__ __forceinline__ float warpSum(float v) {
    #pragma unroll
    for (int o = 16; o > 0; o >>= 1) v += __shfl_xor_sync(0xffffffffu, v, o);
    return v;
}

// ---------------------------------------------------------------------------
// Row softmax over 2048 fp16 logits, in place (fp32 math, fast exp)
// ---------------------------------------------------------------------------
__global__ void __launch_bounds__(256)
softmax_kernel(__half* __restrict__ S)
{
    __half* p = S + (size_t)blockIdx.x * SEQ;
    const int tid  = threadIdx.x;
    const int lane = tid & 31;
    const int wid  = tid >> 5;
    __shared__ float sh[8];

    __half2 hv[4];
    *reinterpret_cast<float4*>(hv) = *reinterpret_cast<const float4*>(&p[tid * 8]);
    float v[8];
    #pragma unroll
    for (int i = 0; i < 4; i++) {
        float2 f = __half22float2(hv[i]);
        v[i*2] = f.x; v[i*2+1] = f.y;
    }

    float m = v[0];
    #pragma unroll
    for (int i = 1; i < 8; i++) m = fmaxf(m, v[i]);
    m = warpMax(m);
    if (lane == 0) sh[wid] = m;
    __syncthreads();
    m = sh[0];
    #pragma unroll
    for (int w = 1; w < 8; w++) m = fmaxf(m, sh[w]);
    __syncthreads();

    float s = 0.f;
    #pragma unroll
    for (int i = 0; i < 8; i++) { v[i] = __expf(v[i] - m); s += v[i]; }
    s = warpSum(s);
    if (lane == 0) sh[wid] = s;
    __syncthreads();
    float tot = sh[0];
    #pragma unroll
    for (int w = 1; w < 8; w++) tot += sh[w];
    float inv = 1.f / tot;

    #pragma unroll
    for (int i = 0; i < 4; i++)
        hv[i] = __floats2half2_rn(v[i*2] * inv, v[i*2+1] * inv);
    *reinterpret_cast<float4*>(&p[tid * 8]) = *reinterpret_cast<float4*>(hv);
}

// ---------------------------------------------------------------------------
// LayerNorm over last dim (512), fp16 input; fp32 and/or fp16 outputs.
// ---------------------------------------------------------------------------
__global__ void __launch_bounds__(128)
layernorm_h(const __half* __restrict__ in, float* __restrict__ out,
            __half* __restrict__ out_h,
            const float* __restrict__ gamma, const float* __restrict__ beta)
{
    const size_t base = (size_t)blockIdx.x * DIM;
    const int tid  = threadIdx.x;
    const int lane = tid & 31;
    const int wid  = tid >> 5;
    __shared__ float shs[4], shq[4];

    __half2 h0 = *reinterpret_cast<const __half2*>(&in[base + tid * 4]);
    __half2 h1 = *reinterpret_cast<const __half2*>(&in[base + tid * 4 + 2]);
    float2 f0 = __half22float2(h0);
    float2 f1 = __half22float2(h1);
    float x0 = f0.x, x1 = f0.y, x2 = f1.x, x3 = f1.y;

    float s  = x0 + x1 + x2 + x3;
    float ss = x0 * x0 + x1 * x1 + x2 * x2 + x3 * x3;
    s  = warpSum(s);
    ss = warpSum(ss);
    if (lane == 0) { shs[wid] = s; shq[wid] = ss; }
    __syncthreads();
    float sum = shs[0] + shs[1] + shs[2] + shs[3];
    float sq  = shq[0] + shq[1] + shq[2] + shq[3];
    float mu  = sum * (1.f / DIM);
    float var = sq * (1.f / DIM) - mu * mu;
    float rs  = rsqrtf(var + 1e-5f);

    float4 gm = *reinterpret_cast<const float4*>(&gamma[tid * 4]);
    float4 bt = *reinterpret_cast<const float4*>(&beta[tid * 4]);
    float o0 = (x0 - mu) * rs * gm.x + bt.x;
    float o1 = (x1 - mu) * rs * gm.y + bt.y;
    float o2 = (x2 - mu) * rs * gm.z + bt.z;
    float o3 = (x3 - mu) * rs * gm.w + bt.w;
    if (out) {
        float4 o = make_float4(o0, o1, o2, o3);
        *reinterpret_cast<float4*>(&out[base + tid * 4]) = o;
    }
    if (out_h) {
        *reinterpret_cast<__half2*>(&out_h[base + tid * 4])     = __floats2half2_rn(o0, o1);
        *reinterpret_cast<__half2*>(&out_h[base + tid * 4 + 2]) = __floats2half2_rn(o2, o3);
    }
}

// ---------------------------------------------------------------------------
// Launch
// ---------------------------------------------------------------------------
extern "C" void kernel_launch(void* const* d_in, const int* in_sizes, int n_in,
                              void* d_out, int out_size)
{
    const float* Noise = (const float*)d_in[0];
    const float* X     = (const float*)d_in[1];
    const float* cond  = (const float*)d_in[2];
    const float* Wg    = (const float*)d_in[3];
    const float* bg    = (const float*)d_in[4];
    const float* W1    = (const float*)d_in[5];
    const float* b1    = (const float*)d_in[6];
    const float* W2    = (const float*)d_in[7];
    const float* b2    = (const float*)d_in[8];
    const float* g1    = (const float*)d_in[9];
    const float* be1   = (const float*)d_in[10];
    const float* g2    = (const float*)d_in[11];
    const float* be2   = (const float*)d_in[12];
    float* out = (float*)d_out;

    __half *fusedh, *attnfh, *attnh, *qh, *hh, *yh, *noiseh, *condh, *xh, *xth, *wgth, *w1th, *w2th;
    cudaGetSymbolAddress((void**)&fusedh, g_fusedh);
    cudaGetSymbolAddress((void**)&attnfh, g_attnfh);
    cudaGetSymbolAddress((void**)&attnh,  g_attnh);
    cudaGetSymbolAddress((void**)&qh,     g_qh);
    cudaGetSymbolAddress((void**)&hh,     g_hh);
    cudaGetSymbolAddress((void**)&yh,     g_yh);
    cudaGetSymbolAddress((void**)&noiseh, g_noiseh);
    cudaGetSymbolAddress((void**)&condh,  g_condh);
    cudaGetSymbolAddress((void**)&xh,     g_xh);
    cudaGetSymbolAddress((void**)&xth,    g_xth);
    cudaGetSymbolAddress((void**)&wgth,   g_wgth);
    cudaGetSymbolAddress((void**)&w1th,   g_w1th);
    cudaGetSymbolAddress((void**)&w2th,   g_w2th);

    cudaFuncSetAttribute(gemm_mma<EPI_GATE, true>,      cudaFuncAttributeMaxDynamicSharedMemorySize, SMEM_BYTES_G);
    cudaFuncSetAttribute(gemm_mma<EPI_SCALE, false>,    cudaFuncAttributeMaxDynamicSharedMemorySize, SMEM_BYTES_G);
    cudaFuncSetAttribute(gemm_mma<EPI_ADD, false>,      cudaFuncAttributeMaxDynamicSharedMemorySize, SMEM_BYTES_G);
    cudaFuncSetAttribute(gemm_mma<EPI_GELU, false>,     cudaFuncAttributeMaxDynamicSharedMemorySize, SMEM_BYTES_G);
    cudaFuncSetAttribute(gemm_mma<EPI_BIAS_RES, false>, cudaFuncAttributeMaxDynamicSharedMemorySize, SMEM_BYTES_G);

    const float scale = 0.04419417382415922f;  // 1/sqrt(512)
    const int NEL = NTOK * DIM;

    // 0. fp16 conversions + transposes
    convert2_h<<<NEL / 4 / 256, 256>>>(Noise, noiseh, cond, condh);
    transpose_h<<<dim3(DIM / 32, 2 * DIM / 32, 1), dim3(32, 8)>>>(Wg, wgth, nullptr, 2 * DIM, DIM);
    transpose_h<<<dim3(2 * DIM / 32, DIM / 32, 1), dim3(32, 8)>>>(W1, w1th, nullptr, DIM, 2 * DIM);
    transpose_h<<<dim3(DIM / 32, 2 * DIM / 32, 1), dim3(32, 8)>>>(W2, w2th, nullptr, 2 * DIM, DIM);
    transpose_h<<<dim3(DIM / 32, SEQ / 32, BATCH), dim3(32, 8)>>>(X, xth, xh, SEQ, DIM);

    // 1. gate+fuse -> fusedh
    gemm_mma<EPI_GATE, true><<<dim3(DIM / BN, NTOK / BM, 1), NTHREADS, SMEM_BYTES_G>>>(
        noiseh, condh, wgth, fusedh,
        2 * DIM, 2 * DIM, 2 * DIM, DIM,
        0, 0, 0, bg, noiseh, condh, 0.f);

    // 2. logits = fused @ X^T * scale -> attnh
    gemm_mma<EPI_SCALE, false><<<dim3(SEQ / BN, SEQ / BM, BATCH), NTHREADS, SMEM_BYTES_G>>>(
        fusedh, nullptr, xh, attnh,
        DIM, DIM, DIM, SEQ,
        (size_t)SEQ * DIM, (size_t)SEQ * DIM, (size_t)SEQ * SEQ,
        nullptr, nullptr, nullptr, scale);

    // 3. softmax in place
    softmax_kernel<<<NTOK, 256>>>(attnh);

    // 4. attnfh = attn @ X + fusedh
    gemm_mma<EPI_ADD, false><<<dim3(DIM / BN, SEQ / BM, BATCH), NTHREADS, SMEM_BYTES_G>>>(
        attnh, nullptr, xth, attnfh,
        SEQ, SEQ, SEQ, DIM,
        (size_t)SEQ * SEQ, (size_t)DIM * SEQ, (size_t)SEQ * DIM,
        nullptr, fusedh, nullptr, 0.f);

    // 5. qh = LN1(attnfh)
    layernorm_h<<<NTOK, 128>>>(attnfh, nullptr, qh, g1, be1);

    // 6. hh = gelu(qh @ W1 + b1)
    gemm_mma<EPI_GELU, false><<<dim3(2 * DIM / BN, NTOK / BM, 1), NTHREADS, SMEM_BYTES_G>>>(
        qh, nullptr, w1th, hh,
        DIM, DIM, DIM, 2 * DIM,
        0, 0, 0, b1, nullptr, nullptr, 0.f);

    // 7. yh = hh @ W2 + b2 + qh
    gemm_mma<EPI_BIAS_RES, false><<<dim3(DIM / BN, NTOK / BM, 1), NTHREADS, SMEM_BYTES_G>>>(
        hh, nullptr, w2th, yh,
        2 * DIM, 2 * DIM, 2 * DIM, DIM,
        0, 0, 0, b2, qh, nullptr, 0.f);

    // 8. out = LN2(yh)
    layernorm_h<<<NTOK, 128>>>(yh, out, nullptr, g2, be2);
}